// round 5
// baseline (speedup 1.0000x reference)
#include <cuda_runtime.h>
#include <math.h>
#include <stdint.h>

// Problem constants
#define BATCH 4
#define SEQ   2048
#define DIM   768

// Scratch (allocation-free: __device__ globals)
__device__ float g_q [(size_t)BATCH * SEQ * DIM];
__device__ float g_k [(size_t)BATCH * SEQ * DIM];
__device__ float g_v [(size_t)BATCH * SEQ * DIM];
__device__ float g_vt[(size_t)BATCH * SEQ * DIM];
__device__ float g_s [(size_t)BATCH * SEQ * SEQ];
__device__ float g_wt[3][DIM * DIM];

// ----------------------------------------------------------------------------
// helpers
// ----------------------------------------------------------------------------
__device__ __forceinline__ uint32_t smem_u32(const void* p) {
    uint32_t a;
    asm("{ .reg .u64 t; cvta.to.shared.u64 t, %1; cvt.u32.u64 %0, t; }"
        : "=r"(a) : "l"(p));
    return a;
}
__device__ __forceinline__ uint32_t f2tf32(float f) {
    uint32_t r;
    asm("cvt.rna.tf32.f32 %0, %1;" : "=r"(r) : "f"(f));
    return r;
}
__device__ __forceinline__ void cp_async16(uint32_t dst, const void* src) {
    asm volatile("cp.async.cg.shared.global [%0], [%1], 16;"
                 :: "r"(dst), "l"(src));
}
__device__ __forceinline__ void cp_commit() {
    asm volatile("cp.async.commit_group;" ::: "memory");
}
__device__ __forceinline__ void cp_wait1() {
    asm volatile("cp.async.wait_group 1;" ::: "memory");
}
__device__ __forceinline__ void cp_wait0() {
    asm volatile("cp.async.wait_group 0;" ::: "memory");
}
__device__ __forceinline__ void mma_tf32(float* c, const uint32_t* a,
                                         const uint32_t* b) {
    asm volatile(
        "mma.sync.aligned.m16n8k8.row.col.f32.tf32.tf32.f32 "
        "{%0,%1,%2,%3}, {%4,%5,%6,%7}, {%8,%9}, {%0,%1,%2,%3};"
        : "+f"(c[0]), "+f"(c[1]), "+f"(c[2]), "+f"(c[3])
        : "r"(a[0]), "r"(a[1]), "r"(a[2]), "r"(a[3]),
          "r"(b[0]), "r"(b[1]));
}

// ----------------------------------------------------------------------------
// tf32 tensor-core GEMM (NT): C = alpha * A @ B^T (+ bias)
//   A: [M,K] row-major (lda), B: [N,K] row-major (ldb), C: [M,N] (ldc)
//   CTA tile 128x128, BK=32, cp.async 2-stage pipeline, 256 threads (8 warps).
//   Warp tile 64x32: 4x4 m16n8k8 atoms. SMEM stride 36 -> conflict-free frags.
//   Requires M%128==0, N%128==0, K%32==0.
// ----------------------------------------------------------------------------
#define SM_STRIDE 36          // 32 floats + 4 pad
#define STAGE_F   (2 * 128 * SM_STRIDE)   // floats per stage (A tile + B tile)

template <bool BIAS>
__global__ __launch_bounds__(256, 2)
void gemm_mma(const float* __restrict__ A, const float* __restrict__ B,
              const float* __restrict__ bias, float* __restrict__ C,
              int K, int lda, int ldb, int ldc, float alpha,
              size_t sA, size_t sB, size_t sC)
{
    extern __shared__ float sm[];

    const int tid  = threadIdx.x;
    const int wid  = tid >> 5;
    const int lane = tid & 31;
    const int grp  = lane >> 2;     // 0..7
    const int tg   = lane & 3;      // 0..3
    const int wm0  = (wid & 1) * 64;    // warp m offset in CTA tile
    const int wn0  = (wid >> 1) * 32;   // warp n offset

    A += (size_t)blockIdx.z * sA;
    B += (size_t)blockIdx.z * sB;
    C += (size_t)blockIdx.z * sC;
    const int m0 = blockIdx.y * 128;
    const int n0 = blockIdx.x * 128;

    // load indices for gmem->smem (16B granules): 1024 granules per matrix
    const int ld_row = tid >> 3;        // 0..31 (+32 per r-pass) -> tile row
    const int ld_seg = tid & 7;         // 16B segment within 128B row

    float acc[4][4][4];
#pragma unroll
    for (int im = 0; im < 4; im++)
#pragma unroll
        for (int in = 0; in < 4; in++)
#pragma unroll
            for (int r = 0; r < 4; r++) acc[im][in][r] = 0.0f;

    const int nch = K >> 5;

    // ---- tile loader (stage = c&1) ----
    auto load_tile = [&](int c) {
        const int kt = c << 5;
        float* as = sm + (c & 1) * STAGE_F;
        float* bs = as + 128 * SM_STRIDE;
        const uint32_t as_u = smem_u32(as);
        const uint32_t bs_u = smem_u32(bs);
#pragma unroll
        for (int r = 0; r < 4; r++) {
            const int row = ld_row + r * 32;
            cp_async16(as_u + (uint32_t)(row * SM_STRIDE + ld_seg * 4) * 4,
                       A + (size_t)(m0 + row) * lda + kt + ld_seg * 4);
        }
#pragma unroll
        for (int r = 0; r < 4; r++) {
            const int row = ld_row + r * 32;
            cp_async16(bs_u + (uint32_t)(row * SM_STRIDE + ld_seg * 4) * 4,
                       B + (size_t)(n0 + row) * ldb + kt + ld_seg * 4);
        }
    };

    load_tile(0);
    cp_commit();

    for (int c = 0; c < nch; c++) {
        if (c + 1 < nch) {
            load_tile(c + 1);
            cp_commit();
            cp_wait1();
        } else {
            cp_wait0();
        }
        __syncthreads();

        const float* as = sm + (c & 1) * STAGE_F;
        const float* bs = as + 128 * SM_STRIDE;

#pragma unroll
        for (int ks = 0; ks < 4; ks++) {
            const int kc = ks * 8 + tg;
            uint32_t af[4][4];
#pragma unroll
            for (int im = 0; im < 4; im++) {
                const float* ap = as + (wm0 + im * 16 + grp) * SM_STRIDE + kc;
                af[im][0] = f2tf32(ap[0]);
                af[im][1] = f2tf32(ap[8 * SM_STRIDE]);
                af[im][2] = f2tf32(ap[4]);
                af[im][3] = f2tf32(ap[8 * SM_STRIDE + 4]);
            }
            uint32_t bf[4][2];
#pragma unroll
            for (int in = 0; in < 4; in++) {
                const float* bp = bs + (wn0 + in * 8 + grp) * SM_STRIDE + kc;
                bf[in][0] = f2tf32(bp[0]);
                bf[in][1] = f2tf32(bp[4]);
            }
#pragma unroll
            for (int im = 0; im < 4; im++)
#pragma unroll
                for (int in = 0; in < 4; in++)
                    mma_tf32(acc[im][in], af[im], bf[in]);
        }
        __syncthreads();
    }

    // ---- epilogue: direct STG.64 per C fragment ----
#pragma unroll
    for (int im = 0; im < 4; im++) {
        const int row = m0 + wm0 + im * 16 + grp;
#pragma unroll
        for (int in = 0; in < 4; in++) {
            const int col = n0 + wn0 + in * 8 + tg * 2;
            float2 v01, v23;
            v01.x = acc[im][in][0] * alpha;
            v01.y = acc[im][in][1] * alpha;
            v23.x = acc[im][in][2] * alpha;
            v23.y = acc[im][in][3] * alpha;
            if (BIAS) {
                const float2 bv = *reinterpret_cast<const float2*>(bias + col);
                v01.x += bv.x; v01.y += bv.y;
                v23.x += bv.x; v23.y += bv.y;
            }
            *reinterpret_cast<float2*>(C + (size_t)row * ldc + col) = v01;
            *reinterpret_cast<float2*>(C + (size_t)(row + 8) * ldc + col) = v23;
        }
    }
}

// ----------------------------------------------------------------------------
// 32x32 tiled transpose: dst[c*R + r] = src[r*C + c]   (batched via z)
// ----------------------------------------------------------------------------
__global__ __launch_bounds__(256)
void transpose_k(const float* __restrict__ src, float* __restrict__ dst,
                 int R, int C, size_t sS, size_t sD)
{
    __shared__ float t[32][33];
    src += (size_t)blockIdx.z * sS;
    dst += (size_t)blockIdx.z * sD;
    const int r0 = blockIdx.y * 32, c0 = blockIdx.x * 32;
    const int tx = threadIdx.x & 31, ty = threadIdx.x >> 5;   // 32 x 8
#pragma unroll
    for (int i = 0; i < 4; i++)
        t[ty + 8 * i][tx] = src[(size_t)(r0 + ty + 8 * i) * C + c0 + tx];
    __syncthreads();
#pragma unroll
    for (int i = 0; i < 4; i++)
        dst[(size_t)(c0 + ty + 8 * i) * R + r0 + tx] = t[tx][ty + 8 * i];
}

// ----------------------------------------------------------------------------
// Row softmax over SEQ=2048 columns. One block (256 threads) per row.
// ----------------------------------------------------------------------------
__global__ __launch_bounds__(256)
void softmax2048(float* __restrict__ S)
{
    float* p = S + (size_t)blockIdx.x * SEQ;
    const int tid = threadIdx.x;
    __shared__ float red_max[8];
    __shared__ float red_sum[8];

    float4* p4 = reinterpret_cast<float4*>(p);
    float4 vals[2];

    float m = -1e30f;
#pragma unroll
    for (int r = 0; r < 2; r++) {
        const float4 v = p4[tid + r * 256];
        vals[r] = v;
        m = fmaxf(m, fmaxf(fmaxf(v.x, v.y), fmaxf(v.z, v.w)));
    }
#pragma unroll
    for (int o = 16; o > 0; o >>= 1)
        m = fmaxf(m, __shfl_xor_sync(0xffffffffu, m, o));
    if ((tid & 31) == 0) red_max[tid >> 5] = m;
    __syncthreads();
    float rm = red_max[0];
#pragma unroll
    for (int i = 1; i < 8; i++) rm = fmaxf(rm, red_max[i]);

    float s = 0.0f;
#pragma unroll
    for (int r = 0; r < 2; r++) {
        float4 v = vals[r];
        v.x = __expf(v.x - rm);
        v.y = __expf(v.y - rm);
        v.z = __expf(v.z - rm);
        v.w = __expf(v.w - rm);
        s += v.x + v.y + v.z + v.w;
        vals[r] = v;
    }
#pragma unroll
    for (int o = 16; o > 0; o >>= 1)
        s += __shfl_xor_sync(0xffffffffu, s, o);
    if ((tid & 31) == 0) red_sum[tid >> 5] = s;
    __syncthreads();
    float total = 0.0f;
#pragma unroll
    for (int i = 0; i < 8; i++) total += red_sum[i];
    const float inv = 1.0f / total;

#pragma unroll
    for (int r = 0; r < 2; r++) {
        float4 v = vals[r];
        v.x *= inv; v.y *= inv; v.z *= inv; v.w *= inv;
        p4[tid + r * 256] = v;
    }
}

// ----------------------------------------------------------------------------
// kernel_launch
// Inputs: x[B,S,D], Wq[D,D], bq[D], Wk, bk, Wv, bv ; output [B,S,D] fp32
// ----------------------------------------------------------------------------
extern "C" void kernel_launch(void* const* d_in, const int* in_sizes, int n_in,
                              void* d_out, int out_size)
{
    const float* x  = (const float*)d_in[0];
    const float* Wq = (const float*)d_in[1];
    const float* bq = (const float*)d_in[2];
    const float* Wk = (const float*)d_in[3];
    const float* bk = (const float*)d_in[4];
    const float* Wv = (const float*)d_in[5];
    const float* bv = (const float*)d_in[6];
    float* out = (float*)d_out;

    float *q, *k, *v, *vt, *s, *wt;
    cudaGetSymbolAddress((void**)&q,  g_q);
    cudaGetSymbolAddress((void**)&k,  g_k);
    cudaGetSymbolAddress((void**)&v,  g_v);
    cudaGetSymbolAddress((void**)&vt, g_vt);
    cudaGetSymbolAddress((void**)&s,  g_s);
    cudaGetSymbolAddress((void**)&wt, g_wt);
    float* wqt = wt;
    float* wkt = wt + (size_t)DIM * DIM;
    float* wvt = wt + 2 * (size_t)DIM * DIM;

    const int SMEM_DYN = 2 * STAGE_F * (int)sizeof(float);   // 73728 B
    cudaFuncSetAttribute(gemm_mma<true>,
                         cudaFuncAttributeMaxDynamicSharedMemorySize, SMEM_DYN);
    cudaFuncSetAttribute(gemm_mma<false>,
                         cudaFuncAttributeMaxDynamicSharedMemorySize, SMEM_DYN);

    const size_t sdSD = (size_t)SEQ * DIM;
    const size_t sdSS = (size_t)SEQ * SEQ;
    const dim3 blk(256);

    // 0) transpose weights: W[D,D] -> W^T (so QKV GEMMs are NT)
    {
        const dim3 g(DIM / 32, DIM / 32, 1);
        transpose_k<<<g, blk>>>(Wq, wqt, DIM, DIM, 0, 0);
        transpose_k<<<g, blk>>>(Wk, wkt, DIM, DIM, 0, 0);
        transpose_k<<<g, blk>>>(Wv, wvt, DIM, DIM, 0, 0);
    }

    // 1) QKV projections: [8192,768] = x @ W^T (NT) + bias
    {
        const dim3 g(DIM / 128, (BATCH * SEQ) / 128, 1);
        gemm_mma<true><<<g, blk, SMEM_DYN>>>(x, wqt, bq, q,
                                             DIM, DIM, DIM, DIM, 1.0f, 0, 0, 0);
        gemm_mma<true><<<g, blk, SMEM_DYN>>>(x, wkt, bk, k,
                                             DIM, DIM, DIM, DIM, 1.0f, 0, 0, 0);
        gemm_mma<true><<<g, blk, SMEM_DYN>>>(x, wvt, bv, v,
                                             DIM, DIM, DIM, DIM, 1.0f, 0, 0, 0);
    }

    // 2) transpose V: [S,D] -> [D,S] per batch (so attn@V is NT)
    {
        const dim3 g(DIM / 32, SEQ / 32, BATCH);
        transpose_k<<<g, blk>>>(v, vt, SEQ, DIM, sdSD, sdSD);
    }

    // 3) scores = Q @ K^T / sqrt(D)  (NT)
    {
        const dim3 g(SEQ / 128, SEQ / 128, BATCH);
        gemm_mma<false><<<g, blk, SMEM_DYN>>>(q, k, nullptr, s,
                                              DIM, DIM, DIM, SEQ,
                                              rsqrtf((float)DIM),
                                              sdSD, sdSD, sdSS);
    }

    // 4) softmax rows
    softmax2048<<<BATCH * SEQ, 256>>>(s);

    // 5) out = attn @ V == s[S,S] @ (vt[D,S])^T  (NT)
    {
        const dim3 g(DIM / 128, SEQ / 128, BATCH);
        gemm_mma<false><<<g, blk, SMEM_DYN>>>(s, vt, nullptr, out,
                                              SEQ, SEQ, SEQ, DIM, 1.0f,
                                              sdSS, sdSD, sdSD);
    }
}

// round 6
// speedup vs baseline: 1.1178x; 1.1178x over previous
#include <cuda_runtime.h>
#include <math.h>
#include <stdint.h>

// Problem constants
#define BATCH 4
#define SEQ   2048
#define DIM   768

// Scratch (allocation-free: __device__ globals)
__device__ float g_xr[(size_t)BATCH * SEQ * DIM];
__device__ float g_q [(size_t)BATCH * SEQ * DIM];
__device__ float g_k [(size_t)BATCH * SEQ * DIM];
__device__ float g_v [(size_t)BATCH * SEQ * DIM];
__device__ float g_vt[(size_t)BATCH * SEQ * DIM];
__device__ float g_s [(size_t)BATCH * SEQ * SEQ];
__device__ float g_wt[3][DIM * DIM];

// ----------------------------------------------------------------------------
// helpers
// ----------------------------------------------------------------------------
__device__ __forceinline__ uint32_t smem_u32(const void* p) {
    uint32_t a;
    asm("{ .reg .u64 t; cvta.to.shared.u64 t, %1; cvt.u32.u64 %0, t; }"
        : "=r"(a) : "l"(p));
    return a;
}
__device__ __forceinline__ float round_tf32(float f) {
    uint32_t r;
    asm("cvt.rna.tf32.f32 %0, %1;" : "=r"(r) : "f"(f));
    return __uint_as_float(r);
}
__device__ __forceinline__ void cp_async16(uint32_t dst, const void* src) {
    asm volatile("cp.async.cg.shared.global [%0], [%1], 16;"
                 :: "r"(dst), "l"(src));
}
__device__ __forceinline__ void cp_commit() {
    asm volatile("cp.async.commit_group;" ::: "memory");
}
__device__ __forceinline__ void cp_wait1() {
    asm volatile("cp.async.wait_group 1;" ::: "memory");
}
__device__ __forceinline__ void cp_wait0() {
    asm volatile("cp.async.wait_group 0;" ::: "memory");
}
__device__ __forceinline__ void ldsm_x4(uint32_t* r, uint32_t addr) {
    asm volatile("ldmatrix.sync.aligned.m8n8.x4.shared.b16 {%0,%1,%2,%3}, [%4];"
                 : "=r"(r[0]), "=r"(r[1]), "=r"(r[2]), "=r"(r[3])
                 : "r"(addr));
}
__device__ __forceinline__ void mma_tf32(float* c, const uint32_t* a,
                                         const uint32_t* b) {
    asm volatile(
        "mma.sync.aligned.m16n8k8.row.col.f32.tf32.tf32.f32 "
        "{%0,%1,%2,%3}, {%4,%5,%6,%7}, {%8,%9}, {%0,%1,%2,%3};"
        : "+f"(c[0]), "+f"(c[1]), "+f"(c[2]), "+f"(c[3])
        : "r"(a[0]), "r"(a[1]), "r"(a[2]), "r"(a[3]),
          "r"(b[0]), "r"(b[1]));
}

// ----------------------------------------------------------------------------
// tf32 tensor-core GEMM (NT): C = alpha * A @ B^T (+ bias) [+ tf32 round]
//   A: [M,K] row-major (lda), B: [N,K] row-major (ldb), C: [M,N] (ldc)
//   INPUTS MUST BE PRE-ROUNDED TO TF32 (mainloop feeds raw bits to mma).
//   CTA tile 128x128, BK=32, cp.async 2-stage pipeline, 256 threads (8 warps).
//   Warp tile 64x32: 4x4 m16n8k8 atoms; ldmatrix.x4 fragment loads.
// ----------------------------------------------------------------------------
#define SM_STRIDE 36          // 32 floats + 4 pad
#define STAGE_F   (2 * 128 * SM_STRIDE)   // floats per stage (A tile + B tile)

template <bool BIAS, bool ROUND>
__global__ __launch_bounds__(256, 2)
void gemm_mma(const float* __restrict__ A, const float* __restrict__ B,
              const float* __restrict__ bias, float* __restrict__ C,
              int K, int lda, int ldb, int ldc, float alpha,
              size_t sA, size_t sB, size_t sC)
{
    extern __shared__ float sm[];

    const int tid  = threadIdx.x;
    const int wid  = tid >> 5;
    const int lane = tid & 31;
    const int grp  = lane >> 2;     // 0..7
    const int tg   = lane & 3;      // 0..3
    const int wm0  = (wid & 1) * 64;    // warp m offset in CTA tile
    const int wn0  = (wid >> 1) * 32;   // warp n offset

    // ldmatrix per-lane address components
    const int lg   = lane >> 3;     // matrix index group 0..3
    const int lrow = lane & 7;      // row within 8x4 matrix

    A += (size_t)blockIdx.z * sA;
    B += (size_t)blockIdx.z * sB;
    C += (size_t)blockIdx.z * sC;
    const int m0 = blockIdx.y * 128;
    const int n0 = blockIdx.x * 128;

    // load indices for gmem->smem (16B granules)
    const int ld_row = tid >> 3;        // 0..31 (+32 per r-pass)
    const int ld_seg = tid & 7;         // 16B segment within 128B row

    float acc[4][4][4];
#pragma unroll
    for (int im = 0; im < 4; im++)
#pragma unroll
        for (int in = 0; in < 4; in++)
#pragma unroll
            for (int r = 0; r < 4; r++) acc[im][in][r] = 0.0f;

    const int nch = K >> 5;

    auto load_tile = [&](int c) {
        const int kt = c << 5;
        float* as = sm + (c & 1) * STAGE_F;
        float* bs = as + 128 * SM_STRIDE;
        const uint32_t as_u = smem_u32(as);
        const uint32_t bs_u = smem_u32(bs);
#pragma unroll
        for (int r = 0; r < 4; r++) {
            const int row = ld_row + r * 32;
            cp_async16(as_u + (uint32_t)(row * SM_STRIDE + ld_seg * 4) * 4,
                       A + (size_t)(m0 + row) * lda + kt + ld_seg * 4);
        }
#pragma unroll
        for (int r = 0; r < 4; r++) {
            const int row = ld_row + r * 32;
            cp_async16(bs_u + (uint32_t)(row * SM_STRIDE + ld_seg * 4) * 4,
                       B + (size_t)(n0 + row) * ldb + kt + ld_seg * 4);
        }
    };

    load_tile(0);
    cp_commit();

    for (int c = 0; c < nch; c++) {
        if (c + 1 < nch) {
            load_tile(c + 1);
            cp_commit();
            cp_wait1();
        } else {
            cp_wait0();
        }
        __syncthreads();

        const float* as = sm + (c & 1) * STAGE_F;
        const float* bs = as + 128 * SM_STRIDE;

        // per-lane ldmatrix base addresses (bytes)
        // A x4: mat g -> rows (g&1)*8, k cols (g>>1)*4
        const uint32_t a_base = smem_u32(as) +
            (uint32_t)(((wm0 + (lg & 1) * 8 + lrow) * SM_STRIDE +
                        (lg >> 1) * 4) * 4);
        // B x4 (two n8 tiles per load): mat g -> n rows (g>>1)*8, k cols (g&1)*4
        const uint32_t b_base = smem_u32(bs) +
            (uint32_t)(((wn0 + (lg >> 1) * 8 + lrow) * SM_STRIDE +
                        (lg & 1) * 4) * 4);

#pragma unroll
        for (int ks = 0; ks < 4; ks++) {
            uint32_t af[4][4];
#pragma unroll
            for (int im = 0; im < 4; im++)
                ldsm_x4(af[im], a_base + im * (16 * SM_STRIDE * 4) + ks * 32);
            uint32_t bf[2][4];   // bf[p] = {in(2p).b0, in(2p).b1, in(2p+1).b0, in(2p+1).b1}
#pragma unroll
            for (int p = 0; p < 2; p++)
                ldsm_x4(bf[p], b_base + p * (16 * SM_STRIDE * 4) + ks * 32);
#pragma unroll
            for (int im = 0; im < 4; im++)
#pragma unroll
                for (int in = 0; in < 4; in++)
                    mma_tf32(acc[im][in], af[im], &bf[in >> 1][(in & 1) * 2]);
        }
        __syncthreads();
    }

    // ---- epilogue: direct STG.64 per C fragment ----
#pragma unroll
    for (int im = 0; im < 4; im++) {
        const int row = m0 + wm0 + im * 16 + grp;
#pragma unroll
        for (int in = 0; in < 4; in++) {
            const int col = n0 + wn0 + in * 8 + tg * 2;
            float2 v01, v23;
            v01.x = acc[im][in][0] * alpha;
            v01.y = acc[im][in][1] * alpha;
            v23.x = acc[im][in][2] * alpha;
            v23.y = acc[im][in][3] * alpha;
            if (BIAS) {
                const float2 bv = *reinterpret_cast<const float2*>(bias + col);
                v01.x += bv.x; v01.y += bv.y;
                v23.x += bv.x; v23.y += bv.y;
            }
            if (ROUND) {
                v01.x = round_tf32(v01.x); v01.y = round_tf32(v01.y);
                v23.x = round_tf32(v23.x); v23.y = round_tf32(v23.y);
            }
            *reinterpret_cast<float2*>(C + (size_t)row * ldc + col) = v01;
            *reinterpret_cast<float2*>(C + (size_t)(row + 8) * ldc + col) = v23;
        }
    }
}

// ----------------------------------------------------------------------------
// elementwise tf32 rounding copy (float4 granularity)
// ----------------------------------------------------------------------------
__global__ __launch_bounds__(256)
void round_copy(const float* __restrict__ src, float* __restrict__ dst)
{
    const int i = blockIdx.x * blockDim.x + threadIdx.x;
    float4 v = reinterpret_cast<const float4*>(src)[i];
    v.x = round_tf32(v.x);
    v.y = round_tf32(v.y);
    v.z = round_tf32(v.z);
    v.w = round_tf32(v.w);
    reinterpret_cast<float4*>(dst)[i] = v;
}

// ----------------------------------------------------------------------------
// 32x32 tiled transpose (+ optional tf32 rounding): dst[c*R+r] = src[r*C+c]
// ----------------------------------------------------------------------------
template <bool ROUND>
__global__ __launch_bounds__(256)
void transpose_k(const float* __restrict__ src, float* __restrict__ dst,
                 int R, int C, size_t sS, size_t sD)
{
    __shared__ float t[32][33];
    src += (size_t)blockIdx.z * sS;
    dst += (size_t)blockIdx.z * sD;
    const int r0 = blockIdx.y * 32, c0 = blockIdx.x * 32;
    const int tx = threadIdx.x & 31, ty = threadIdx.x >> 5;   // 32 x 8
#pragma unroll
    for (int i = 0; i < 4; i++) {
        float v = src[(size_t)(r0 + ty + 8 * i) * C + c0 + tx];
        t[ty + 8 * i][tx] = ROUND ? round_tf32(v) : v;
    }
    __syncthreads();
#pragma unroll
    for (int i = 0; i < 4; i++)
        dst[(size_t)(c0 + ty + 8 * i) * R + r0 + tx] = t[tx][ty + 8 * i];
}

// ----------------------------------------------------------------------------
// Row softmax over SEQ=2048 columns (tf32-rounded output).
// ----------------------------------------------------------------------------
__global__ __launch_bounds__(256)
void softmax2048(float* __restrict__ S)
{
    float* p = S + (size_t)blockIdx.x * SEQ;
    const int tid = threadIdx.x;
    __shared__ float red_max[8];
    __shared__ float red_sum[8];

    float4* p4 = reinterpret_cast<float4*>(p);
    float4 vals[2];

    float m = -1e30f;
#pragma unroll
    for (int r = 0; r < 2; r++) {
        const float4 v = p4[tid + r * 256];
        vals[r] = v;
        m = fmaxf(m, fmaxf(fmaxf(v.x, v.y), fmaxf(v.z, v.w)));
    }
#pragma unroll
    for (int o = 16; o > 0; o >>= 1)
        m = fmaxf(m, __shfl_xor_sync(0xffffffffu, m, o));
    if ((tid & 31) == 0) red_max[tid >> 5] = m;
    __syncthreads();
    float rm = red_max[0];
#pragma unroll
    for (int i = 1; i < 8; i++) rm = fmaxf(rm, red_max[i]);

    float s = 0.0f;
#pragma unroll
    for (int r = 0; r < 2; r++) {
        float4 v = vals[r];
        v.x = __expf(v.x - rm);
        v.y = __expf(v.y - rm);
        v.z = __expf(v.z - rm);
        v.w = __expf(v.w - rm);
        s += v.x + v.y + v.z + v.w;
        vals[r] = v;
    }
#pragma unroll
    for (int o = 16; o > 0; o >>= 1)
        s += __shfl_xor_sync(0xffffffffu, s, o);
    if ((tid & 31) == 0) red_sum[tid >> 5] = s;
    __syncthreads();
    float total = 0.0f;
#pragma unroll
    for (int i = 0; i < 8; i++) total += red_sum[i];
    const float inv = 1.0f / total;

#pragma unroll
    for (int r = 0; r < 2; r++) {
        float4 v = vals[r];
        v.x = round_tf32(v.x * inv);
        v.y = round_tf32(v.y * inv);
        v.z = round_tf32(v.z * inv);
        v.w = round_tf32(v.w * inv);
        p4[tid + r * 256] = v;
    }
}

// ----------------------------------------------------------------------------
// kernel_launch
// Inputs: x[B,S,D], Wq[D,D], bq[D], Wk, bk, Wv, bv ; output [B,S,D] fp32
// ----------------------------------------------------------------------------
extern "C" void kernel_launch(void* const* d_in, const int* in_sizes, int n_in,
                              void* d_out, int out_size)
{
    const float* x  = (const float*)d_in[0];
    const float* Wq = (const float*)d_in[1];
    const float* bq = (const float*)d_in[2];
    const float* Wk = (const float*)d_in[3];
    const float* bk = (const float*)d_in[4];
    const float* Wv = (const float*)d_in[5];
    const float* bv = (const float*)d_in[6];
    float* out = (float*)d_out;

    float *xr, *q, *k, *v, *vt, *s, *wt;
    cudaGetSymbolAddress((void**)&xr, g_xr);
    cudaGetSymbolAddress((void**)&q,  g_q);
    cudaGetSymbolAddress((void**)&k,  g_k);
    cudaGetSymbolAddress((void**)&v,  g_v);
    cudaGetSymbolAddress((void**)&vt, g_vt);
    cudaGetSymbolAddress((void**)&s,  g_s);
    cudaGetSymbolAddress((void**)&wt, g_wt);
    float* wqt = wt;
    float* wkt = wt + (size_t)DIM * DIM;
    float* wvt = wt + 2 * (size_t)DIM * DIM;

    const int SMEM_DYN = 2 * STAGE_F * (int)sizeof(float);   // 73728 B
    cudaFuncSetAttribute(gemm_mma<true, true>,
                         cudaFuncAttributeMaxDynamicSharedMemorySize, SMEM_DYN);
    cudaFuncSetAttribute(gemm_mma<false, true>,
                         cudaFuncAttributeMaxDynamicSharedMemorySize, SMEM_DYN);
    cudaFuncSetAttribute(gemm_mma<false, false>,
                         cudaFuncAttributeMaxDynamicSharedMemorySize, SMEM_DYN);

    const size_t sdSD = (size_t)SEQ * DIM;
    const size_t sdSS = (size_t)SEQ * SEQ;
    const dim3 blk(256);

    // 0a) pre-round x to tf32
    round_copy<<<(BATCH * SEQ * DIM / 4 + 255) / 256, 256>>>(x, xr);

    // 0b) transpose + round weights: W[D,D] -> tf32(W^T)
    {
        const dim3 g(DIM / 32, DIM / 32, 1);
        transpose_k<true><<<g, blk>>>(Wq, wqt, DIM, DIM, 0, 0);
        transpose_k<true><<<g, blk>>>(Wk, wkt, DIM, DIM, 0, 0);
        transpose_k<true><<<g, blk>>>(Wv, wvt, DIM, DIM, 0, 0);
    }

    // 1) QKV projections (outputs rounded to tf32 for downstream MMAs)
    {
        const dim3 g(DIM / 128, (BATCH * SEQ) / 128, 1);
        gemm_mma<true, true><<<g, blk, SMEM_DYN>>>(xr, wqt, bq, q,
                                                   DIM, DIM, DIM, DIM, 1.0f, 0, 0, 0);
        gemm_mma<true, true><<<g, blk, SMEM_DYN>>>(xr, wkt, bk, k,
                                                   DIM, DIM, DIM, DIM, 1.0f, 0, 0, 0);
        gemm_mma<true, true><<<g, blk, SMEM_DYN>>>(xr, wvt, bv, v,
                                                   DIM, DIM, DIM, DIM, 1.0f, 0, 0, 0);
    }

    // 2) transpose V (already tf32-rounded): [S,D] -> [D,S] per batch
    {
        const dim3 g(DIM / 32, SEQ / 32, BATCH);
        transpose_k<false><<<g, blk>>>(v, vt, SEQ, DIM, sdSD, sdSD);
    }

    // 3) scores = Q @ K^T / sqrt(D)  (NT; raw fp32 out, softmax rounds)
    {
        const dim3 g(SEQ / 128, SEQ / 128, BATCH);
        gemm_mma<false, false><<<g, blk, SMEM_DYN>>>(q, k, nullptr, s,
                                                     DIM, DIM, DIM, SEQ,
                                                     rsqrtf((float)DIM),
                                                     sdSD, sdSD, sdSS);
    }

    // 4) softmax rows (rounds probs to tf32)
    softmax2048<<<BATCH * SEQ, 256>>>(s);

    // 5) out = attn @ V == s[S,S] @ (vt[D,S])^T  (NT)
    {
        const dim3 g(DIM / 128, SEQ / 128, BATCH);
        gemm_mma<false, false><<<g, blk, SMEM_DYN>>>(s, vt, nullptr, out,
                                                     SEQ, SEQ, SEQ, DIM, 1.0f,
                                                     sdSS, sdSD, sdSD);
    }
}

// round 7
// speedup vs baseline: 1.7320x; 1.5495x over previous
#include <cuda_runtime.h>
#include <cuda_fp16.h>
#include <math.h>
#include <stdint.h>

// Problem constants
#define BATCH 4
#define SEQ   2048
#define DIM   768

// Scratch (allocation-free: __device__ globals)
__device__ __half g_xh[(size_t)BATCH * SEQ * DIM];
__device__ __half g_q [(size_t)BATCH * SEQ * DIM];
__device__ __half g_k [(size_t)BATCH * SEQ * DIM];
__device__ __half g_v [(size_t)BATCH * SEQ * DIM];
__device__ __half g_vt[(size_t)BATCH * SEQ * DIM];
__device__ float  g_s [(size_t)BATCH * SEQ * SEQ];
__device__ __half g_p [(size_t)BATCH * SEQ * SEQ];
__device__ __half g_wt[3][DIM * DIM];

// ----------------------------------------------------------------------------
// helpers
// ----------------------------------------------------------------------------
__device__ __forceinline__ uint32_t smem_u32(const void* p) {
    uint32_t a;
    asm("{ .reg .u64 t; cvta.to.shared.u64 t, %1; cvt.u32.u64 %0, t; }"
        : "=r"(a) : "l"(p));
    return a;
}
__device__ __forceinline__ void cp_async16(uint32_t dst, const void* src) {
    asm volatile("cp.async.cg.shared.global [%0], [%1], 16;"
                 :: "r"(dst), "l"(src));
}
__device__ __forceinline__ void cp_commit() {
    asm volatile("cp.async.commit_group;" ::: "memory");
}
__device__ __forceinline__ void cp_wait1() {
    asm volatile("cp.async.wait_group 1;" ::: "memory");
}
__device__ __forceinline__ void cp_wait0() {
    asm volatile("cp.async.wait_group 0;" ::: "memory");
}
__device__ __forceinline__ void ldsm_x4(uint32_t* r, uint32_t addr) {
    asm volatile("ldmatrix.sync.aligned.m8n8.x4.shared.b16 {%0,%1,%2,%3}, [%4];"
                 : "=r"(r[0]), "=r"(r[1]), "=r"(r[2]), "=r"(r[3])
                 : "r"(addr));
}
// m16n8k16 fp16 MMA, fp32 accumulate
__device__ __forceinline__ void mma_f16(float* c, const uint32_t* a,
                                        uint32_t b0, uint32_t b1) {
    asm volatile(
        "mma.sync.aligned.m16n8k16.row.col.f32.f16.f16.f32 "
        "{%0,%1,%2,%3}, {%4,%5,%6,%7}, {%8,%9}, {%0,%1,%2,%3};"
        : "+f"(c[0]), "+f"(c[1]), "+f"(c[2]), "+f"(c[3])
        : "r"(a[0]), "r"(a[1]), "r"(a[2]), "r"(a[3]),
          "r"(b0), "r"(b1));
}

// ----------------------------------------------------------------------------
// fp16 tensor-core GEMM (NT): C = alpha * A @ B^T (+ bias)
//   A: [M,K] half row-major (lda), B: [N,K] half row-major (ldb)
//   C: [M,N] float or half (ldc). fp32 accumulate throughout.
//   CTA tile 128x128, BK=64, cp.async 2-stage pipeline, 256 threads (8 warps).
//   Warp tile 64x32: 4x4 m16n8k16 atoms; ldmatrix.x4 fragment loads.
//   SMEM row stride 72 halfs (144B) -> conflict-free ldmatrix.
// ----------------------------------------------------------------------------
#define SH        72                     // halfs per smem row (64 + 8 pad)
#define MAT_H     (128 * SH)             // halfs per matrix tile
#define STAGE_H   (2 * MAT_H)            // halfs per stage (A + B)

template <typename CT, bool BIAS>
__global__ __launch_bounds__(256, 2)
void gemm_h(const __half* __restrict__ A, const __half* __restrict__ B,
            const float* __restrict__ bias, CT* __restrict__ C,
            int K, int lda, int ldb, int ldc, float alpha,
            size_t sA, size_t sB, size_t sC)
{
    extern __shared__ __half smh[];

    const int tid  = threadIdx.x;
    const int wid  = tid >> 5;
    const int lane = tid & 31;
    const int grp  = lane >> 2;         // 0..7
    const int tg   = lane & 3;          // 0..3
    const int wm0  = (wid & 1) * 64;    // warp m offset
    const int wn0  = (wid >> 1) * 32;   // warp n offset
    const int lg   = lane >> 3;         // ldmatrix matrix group 0..3
    const int lrow = lane & 7;          // row within 8x8 matrix

    A += (size_t)blockIdx.z * sA;
    B += (size_t)blockIdx.z * sB;
    C += (size_t)blockIdx.z * sC;
    const int m0 = blockIdx.y * 128;
    const int n0 = blockIdx.x * 128;

    // gmem->smem: 16B (8-half) granules; 8 segs per 64-half row, 128 rows
    const int ld_row = tid >> 3;        // 0..31 (+32 per pass)
    const int ld_seg = tid & 7;

    float acc[4][4][4];
#pragma unroll
    for (int im = 0; im < 4; im++)
#pragma unroll
        for (int in = 0; in < 4; in++)
#pragma unroll
            for (int r = 0; r < 4; r++) acc[im][in][r] = 0.0f;

    const int nch = K >> 6;             // K chunks of 64

    auto load_tile = [&](int c) {
        const int kt = c << 6;
        __half* as = smh + (c & 1) * STAGE_H;
        __half* bs = as + MAT_H;
        const uint32_t as_u = smem_u32(as);
        const uint32_t bs_u = smem_u32(bs);
#pragma unroll
        for (int r = 0; r < 4; r++) {
            const int row = ld_row + r * 32;
            cp_async16(as_u + (uint32_t)(row * SH + ld_seg * 8) * 2,
                       A + (size_t)(m0 + row) * lda + kt + ld_seg * 8);
        }
#pragma unroll
        for (int r = 0; r < 4; r++) {
            const int row = ld_row + r * 32;
            cp_async16(bs_u + (uint32_t)(row * SH + ld_seg * 8) * 2,
                       B + (size_t)(n0 + row) * ldb + kt + ld_seg * 8);
        }
    };

    load_tile(0);
    cp_commit();

    for (int c = 0; c < nch; c++) {
        if (c + 1 < nch) {
            load_tile(c + 1);
            cp_commit();
            cp_wait1();
        } else {
            cp_wait0();
        }
        __syncthreads();

        const __half* as = smh + (c & 1) * STAGE_H;
        const __half* bs = as + MAT_H;

        // ldmatrix base addrs (bytes). mat g: rows (g&1)*8, k-halfs (g>>1)*8
        const uint32_t a_base = smem_u32(as) +
            (uint32_t)(((wm0 + (lg & 1) * 8 + lrow) * SH + (lg >> 1) * 8) * 2);
        const uint32_t b_base = smem_u32(bs) +
            (uint32_t)(((wn0 + (lg & 1) * 8 + lrow) * SH + (lg >> 1) * 8) * 2);

#pragma unroll
        for (int ks = 0; ks < 4; ks++) {     // 4 x k16 steps
            uint32_t af[4][4];
#pragma unroll
            for (int im = 0; im < 4; im++)
                ldsm_x4(af[im], a_base + im * (16 * SH * 2) + ks * 32);
            // bf[p]: {n-tile 2p k0-7, 2p+1 k0-7, 2p k8-15, 2p+1 k8-15}
            uint32_t bf[2][4];
#pragma unroll
            for (int p = 0; p < 2; p++)
                ldsm_x4(bf[p], b_base + p * (16 * SH * 2) + ks * 32);
#pragma unroll
            for (int im = 0; im < 4; im++)
#pragma unroll
                for (int in = 0; in < 4; in++)
                    mma_f16(acc[im][in], af[im],
                            bf[in >> 1][in & 1], bf[in >> 1][(in & 1) + 2]);
        }
        __syncthreads();
    }

    // ---- epilogue ----
#pragma unroll
    for (int im = 0; im < 4; im++) {
        const int row = m0 + wm0 + im * 16 + grp;
#pragma unroll
        for (int in = 0; in < 4; in++) {
            const int col = n0 + wn0 + in * 8 + tg * 2;
            float2 v01, v23;
            v01.x = acc[im][in][0] * alpha;
            v01.y = acc[im][in][1] * alpha;
            v23.x = acc[im][in][2] * alpha;
            v23.y = acc[im][in][3] * alpha;
            if (BIAS) {
                const float2 bv = *reinterpret_cast<const float2*>(bias + col);
                v01.x += bv.x; v01.y += bv.y;
                v23.x += bv.x; v23.y += bv.y;
            }
            if (sizeof(CT) == 2) {   // half output
                __half2* c0 = reinterpret_cast<__half2*>(
                    (__half*)C + (size_t)row * ldc + col);
                __half2* c1 = reinterpret_cast<__half2*>(
                    (__half*)C + (size_t)(row + 8) * ldc + col);
                *c0 = __floats2half2_rn(v01.x, v01.y);
                *c1 = __floats2half2_rn(v23.x, v23.y);
            } else {                 // float output
                *reinterpret_cast<float2*>(
                    (float*)C + (size_t)row * ldc + col) = v01;
                *reinterpret_cast<float2*>(
                    (float*)C + (size_t)(row + 8) * ldc + col) = v23;
            }
        }
    }
}

// ----------------------------------------------------------------------------
// fp32 -> fp16 elementwise copy (float4 -> 4 halfs)
// ----------------------------------------------------------------------------
__global__ __launch_bounds__(256)
void f32_to_f16(const float* __restrict__ src, __half* __restrict__ dst)
{
    const int i = blockIdx.x * blockDim.x + threadIdx.x;
    const float4 v = reinterpret_cast<const float4*>(src)[i];
    __half2* d = reinterpret_cast<__half2*>(dst) + i * 2;
    d[0] = __floats2half2_rn(v.x, v.y);
    d[1] = __floats2half2_rn(v.z, v.w);
}

// ----------------------------------------------------------------------------
// 32x32 tiled transpose, fp32 src -> fp16 dst: dst[c*R+r] = (half)src[r*C+c]
// ----------------------------------------------------------------------------
__global__ __launch_bounds__(256)
void trans_f2h(const float* __restrict__ src, __half* __restrict__ dst,
               int R, int C)
{
    __shared__ float t[32][33];
    const int r0 = blockIdx.y * 32, c0 = blockIdx.x * 32;
    const int tx = threadIdx.x & 31, ty = threadIdx.x >> 5;
#pragma unroll
    for (int i = 0; i < 4; i++)
        t[ty + 8 * i][tx] = src[(size_t)(r0 + ty + 8 * i) * C + c0 + tx];
    __syncthreads();
#pragma unroll
    for (int i = 0; i < 4; i++)
        dst[(size_t)(c0 + ty + 8 * i) * R + r0 + tx] =
            __float2half_rn(t[tx][ty + 8 * i]);
}

// ----------------------------------------------------------------------------
// 32x32 tiled transpose, fp16 -> fp16 (batched via z)
// ----------------------------------------------------------------------------
__global__ __launch_bounds__(256)
void trans_h2h(const __half* __restrict__ src, __half* __restrict__ dst,
               int R, int C, size_t sS, size_t sD)
{
    __shared__ __half t[32][34];
    src += (size_t)blockIdx.z * sS;
    dst += (size_t)blockIdx.z * sD;
    const int r0 = blockIdx.y * 32, c0 = blockIdx.x * 32;
    const int tx = threadIdx.x & 31, ty = threadIdx.x >> 5;
#pragma unroll
    for (int i = 0; i < 4; i++)
        t[ty + 8 * i][tx] = src[(size_t)(r0 + ty + 8 * i) * C + c0 + tx];
    __syncthreads();
#pragma unroll
    for (int i = 0; i < 4; i++)
        dst[(size_t)(c0 + ty + 8 * i) * R + r0 + tx] = t[tx][ty + 8 * i];
}

// ----------------------------------------------------------------------------
// Row softmax over SEQ=2048 fp32 scores -> fp16 probs.
// ----------------------------------------------------------------------------
__global__ __launch_bounds__(256)
void softmax2048(const float* __restrict__ S, __half* __restrict__ P)
{
    const float* p = S + (size_t)blockIdx.x * SEQ;
    __half2* po = reinterpret_cast<__half2*>(P + (size_t)blockIdx.x * SEQ);
    const int tid = threadIdx.x;
    __shared__ float red_max[8];
    __shared__ float red_sum[8];

    const float4* p4 = reinterpret_cast<const float4*>(p);
    float4 vals[2];

    float m = -1e30f;
#pragma unroll
    for (int r = 0; r < 2; r++) {
        const float4 v = p4[tid + r * 256];
        vals[r] = v;
        m = fmaxf(m, fmaxf(fmaxf(v.x, v.y), fmaxf(v.z, v.w)));
    }
#pragma unroll
    for (int o = 16; o > 0; o >>= 1)
        m = fmaxf(m, __shfl_xor_sync(0xffffffffu, m, o));
    if ((tid & 31) == 0) red_max[tid >> 5] = m;
    __syncthreads();
    float rm = red_max[0];
#pragma unroll
    for (int i = 1; i < 8; i++) rm = fmaxf(rm, red_max[i]);

    float s = 0.0f;
#pragma unroll
    for (int r = 0; r < 2; r++) {
        float4 v = vals[r];
        v.x = __expf(v.x - rm);
        v.y = __expf(v.y - rm);
        v.z = __expf(v.z - rm);
        v.w = __expf(v.w - rm);
        s += v.x + v.y + v.z + v.w;
        vals[r] = v;
    }
#pragma unroll
    for (int o = 16; o > 0; o >>= 1)
        s += __shfl_xor_sync(0xffffffffu, s, o);
    if ((tid & 31) == 0) red_sum[tid >> 5] = s;
    __syncthreads();
    float total = 0.0f;
#pragma unroll
    for (int i = 0; i < 8; i++) total += red_sum[i];
    const float inv = 1.0f / total;

#pragma unroll
    for (int r = 0; r < 2; r++) {
        const float4 v = vals[r];
        const int i = tid + r * 256;
        po[i * 2 + 0] = __floats2half2_rn(v.x * inv, v.y * inv);
        po[i * 2 + 1] = __floats2half2_rn(v.z * inv, v.w * inv);
    }
}

// ----------------------------------------------------------------------------
// kernel_launch
// Inputs: x[B,S,D], Wq[D,D], bq[D], Wk, bk, Wv, bv ; output [B,S,D] fp32
// ----------------------------------------------------------------------------
extern "C" void kernel_launch(void* const* d_in, const int* in_sizes, int n_in,
                              void* d_out, int out_size)
{
    const float* x  = (const float*)d_in[0];
    const float* Wq = (const float*)d_in[1];
    const float* bq = (const float*)d_in[2];
    const float* Wk = (const float*)d_in[3];
    const float* bk = (const float*)d_in[4];
    const float* Wv = (const float*)d_in[5];
    const float* bv = (const float*)d_in[6];
    float* out = (float*)d_out;

    __half *xh, *q, *k, *v, *vt, *p, *wt;
    float* s;
    cudaGetSymbolAddress((void**)&xh, g_xh);
    cudaGetSymbolAddress((void**)&q,  g_q);
    cudaGetSymbolAddress((void**)&k,  g_k);
    cudaGetSymbolAddress((void**)&v,  g_v);
    cudaGetSymbolAddress((void**)&vt, g_vt);
    cudaGetSymbolAddress((void**)&s,  g_s);
    cudaGetSymbolAddress((void**)&p,  g_p);
    cudaGetSymbolAddress((void**)&wt, g_wt);
    __half* wqt = wt;
    __half* wkt = wt + (size_t)DIM * DIM;
    __half* wvt = wt + 2 * (size_t)DIM * DIM;

    const int SMEM_DYN = 2 * STAGE_H * (int)sizeof(__half);   // 73728 B
    cudaFuncSetAttribute((const void*)gemm_h<__half, true>,
                         cudaFuncAttributeMaxDynamicSharedMemorySize, SMEM_DYN);
    cudaFuncSetAttribute((const void*)gemm_h<float, false>,
                         cudaFuncAttributeMaxDynamicSharedMemorySize, SMEM_DYN);

    const size_t sdSD = (size_t)SEQ * DIM;
    const size_t sdSS = (size_t)SEQ * SEQ;
    const dim3 blk(256);

    // 0a) x -> fp16
    f32_to_f16<<<(BATCH * SEQ * DIM / 4 + 255) / 256, 256>>>(x, xh);

    // 0b) transpose weights to fp16: W[D,D] -> half(W^T)
    {
        const dim3 g(DIM / 32, DIM / 32, 1);
        trans_f2h<<<g, blk>>>(Wq, wqt, DIM, DIM);
        trans_f2h<<<g, blk>>>(Wk, wkt, DIM, DIM);
        trans_f2h<<<g, blk>>>(Wv, wvt, DIM, DIM);
    }

    // 1) QKV projections (fp16 out): [8192,768] = x @ W^T + bias
    {
        const dim3 g(DIM / 128, (BATCH * SEQ) / 128, 1);
        gemm_h<__half, true><<<g, blk, SMEM_DYN>>>(xh, wqt, bq, q,
                                                   DIM, DIM, DIM, DIM, 1.0f,
                                                   0, 0, 0);
        gemm_h<__half, true><<<g, blk, SMEM_DYN>>>(xh, wkt, bk, k,
                                                   DIM, DIM, DIM, DIM, 1.0f,
                                                   0, 0, 0);
        gemm_h<__half, true><<<g, blk, SMEM_DYN>>>(xh, wvt, bv, v,
                                                   DIM, DIM, DIM, DIM, 1.0f,
                                                   0, 0, 0);
    }

    // 2) transpose V: [S,D] -> [D,S] per batch (fp16)
    {
        const dim3 g(DIM / 32, SEQ / 32, BATCH);
        trans_h2h<<<g, blk>>>(v, vt, SEQ, DIM, sdSD, sdSD);
    }

    // 3) scores = Q @ K^T / sqrt(D)  (NT, fp32 out)
    {
        const dim3 g(SEQ / 128, SEQ / 128, BATCH);
        gemm_h<float, false><<<g, blk, SMEM_DYN>>>(q, k, nullptr, s,
                                                   DIM, DIM, DIM, SEQ,
                                                   rsqrtf((float)DIM),
                                                   sdSD, sdSD, sdSS);
    }

    // 4) softmax rows: fp32 scores -> fp16 probs
    softmax2048<<<BATCH * SEQ, 256>>>(s, p);

    // 5) out = P @ V == p[S,S] @ (vt[D,S])^T  (NT, fp32 out)
    {
        const dim3 g(DIM / 128, SEQ / 128, BATCH);
        gemm_h<float, false><<<g, blk, SMEM_DYN>>>(p, vt, nullptr, out,
                                                   SEQ, SEQ, SEQ, DIM, 1.0f,
                                                   sdSS, sdSD, sdSD);
    }
}

// round 8
// speedup vs baseline: 1.8213x; 1.0516x over previous
#include <cuda_runtime.h>
#include <cuda_fp16.h>
#include <math.h>
#include <stdint.h>

// Problem constants
#define BATCH 4
#define SEQ   2048
#define DIM   768
#define NQKV  (3 * DIM)        // 2304

// Scratch (allocation-free: __device__ globals)
__device__ __half g_xh  [(size_t)BATCH * SEQ * DIM];
__device__ __half g_qkv [(size_t)BATCH * SEQ * NQKV];
__device__ __half g_vt  [(size_t)BATCH * SEQ * DIM];
__device__ float  g_s   [(size_t)BATCH * SEQ * SEQ];
__device__ __half g_p   [(size_t)BATCH * SEQ * SEQ];
__device__ __half g_wt  [(size_t)NQKV * DIM];
__device__ float  g_bc  [NQKV];

// ----------------------------------------------------------------------------
// helpers
// ----------------------------------------------------------------------------
__device__ __forceinline__ uint32_t smem_u32(const void* p) {
    uint32_t a;
    asm("{ .reg .u64 t; cvta.to.shared.u64 t, %1; cvt.u32.u64 %0, t; }"
        : "=r"(a) : "l"(p));
    return a;
}
__device__ __forceinline__ void cp_async16(uint32_t dst, const void* src) {
    asm volatile("cp.async.cg.shared.global [%0], [%1], 16;"
                 :: "r"(dst), "l"(src));
}
__device__ __forceinline__ void cp_commit() {
    asm volatile("cp.async.commit_group;" ::: "memory");
}
template <int N>
__device__ __forceinline__ void cp_wait() {
    asm volatile("cp.async.wait_group %0;" :: "n"(N) : "memory");
}
__device__ __forceinline__ void ldsm_x4(uint32_t* r, uint32_t addr) {
    asm volatile("ldmatrix.sync.aligned.m8n8.x4.shared.b16 {%0,%1,%2,%3}, [%4];"
                 : "=r"(r[0]), "=r"(r[1]), "=r"(r[2]), "=r"(r[3])
                 : "r"(addr));
}
__device__ __forceinline__ void mma_f16(float* c, const uint32_t* a,
                                        uint32_t b0, uint32_t b1) {
    asm volatile(
        "mma.sync.aligned.m16n8k16.row.col.f32.f16.f16.f32 "
        "{%0,%1,%2,%3}, {%4,%5,%6,%7}, {%8,%9}, {%0,%1,%2,%3};"
        : "+f"(c[0]), "+f"(c[1]), "+f"(c[2]), "+f"(c[3])
        : "r"(a[0]), "r"(a[1]), "r"(a[2]), "r"(a[3]),
          "r"(b0), "r"(b1));
}

// ----------------------------------------------------------------------------
// fp16 tensor-core GEMM (NT): C = scale * (A @ B^T + bias)
//   A: [M,K] half row-major (lda), B: [N,K] half row-major (ldb)
//   C: [M,N] float or half (ldc). fp32 accumulate.
//   CTA tile 128x128, 4 warps, warp tile 64x64 (4x8 m16n8k16 atoms).
//   BK=64, 3-stage cp.async pipeline. SMEM row stride 72 halfs (144B).
//   QKVF: per-column scale — cols < DIM get alpha (Q pre-scale), else 1.
// ----------------------------------------------------------------------------
#define SH        72
#define MAT_H     (128 * SH)
#define STAGE_H   (2 * MAT_H)            // A tile + B tile (halfs)
#define NSTAGE    3

template <typename CT, bool BIAS, bool QKVF>
__global__ __launch_bounds__(128)
void gemm_h(const __half* __restrict__ A, const __half* __restrict__ B,
            const float* __restrict__ bias, CT* __restrict__ C,
            int K, int lda, int ldb, int ldc, float alpha,
            size_t sA, size_t sB, size_t sC)
{
    extern __shared__ __half smh[];

    const int tid  = threadIdx.x;
    const int wid  = tid >> 5;
    const int lane = tid & 31;
    const int grp  = lane >> 2;
    const int tg   = lane & 3;
    const int wm0  = (wid & 1) * 64;
    const int wn0  = (wid >> 1) * 64;
    const int lg   = lane >> 3;
    const int lrow = lane & 7;

    A += (size_t)blockIdx.z * sA;
    B += (size_t)blockIdx.z * sB;
    C += (size_t)blockIdx.z * sC;
    const int m0 = blockIdx.y * 128;
    const int n0 = blockIdx.x * 128;

    // gmem->smem: 16B granules; 8 segs per 64-half row; 128 threads
    const int ld_row = tid >> 3;        // 0..15 (+16 per pass, 8 passes)
    const int ld_seg = tid & 7;

    float acc[4][8][4];
#pragma unroll
    for (int im = 0; im < 4; im++)
#pragma unroll
        for (int in = 0; in < 8; in++)
#pragma unroll
            for (int r = 0; r < 4; r++) acc[im][in][r] = 0.0f;

    const int nch = K >> 6;

    auto load_tile = [&](int c) {
        const int kt = c << 6;
        __half* as = smh + (c % NSTAGE) * STAGE_H;
        __half* bs = as + MAT_H;
        const uint32_t as_u = smem_u32(as);
        const uint32_t bs_u = smem_u32(bs);
#pragma unroll
        for (int r = 0; r < 8; r++) {
            const int row = ld_row + r * 16;
            cp_async16(as_u + (uint32_t)(row * SH + ld_seg * 8) * 2,
                       A + (size_t)(m0 + row) * lda + kt + ld_seg * 8);
        }
#pragma unroll
        for (int r = 0; r < 8; r++) {
            const int row = ld_row + r * 16;
            cp_async16(bs_u + (uint32_t)(row * SH + ld_seg * 8) * 2,
                       B + (size_t)(n0 + row) * ldb + kt + ld_seg * 8);
        }
    };

    load_tile(0);
    cp_commit();
    load_tile(1);
    cp_commit();

    for (int c = 0; c < nch; c++) {
        cp_wait<1>();          // stage c resident (c+1 may be in flight)
        __syncthreads();       // visibility + all warps done with stage c-1

        if (c + 2 < nch) {     // prefetch into buffer (c+2)%3 == (c-1)%3 (free)
            load_tile(c + 2);
            cp_commit();
        }

        const __half* as = smh + (c % NSTAGE) * STAGE_H;
        const __half* bs = as + MAT_H;

        const uint32_t a_base = smem_u32(as) +
            (uint32_t)(((wm0 + (lg & 1) * 8 + lrow) * SH + (lg >> 1) * 8) * 2);
        const uint32_t b_base = smem_u32(bs) +
            (uint32_t)(((wn0 + (lg & 1) * 8 + lrow) * SH + (lg >> 1) * 8) * 2);

#pragma unroll
        for (int ks = 0; ks < 4; ks++) {
            uint32_t af[4][4];
#pragma unroll
            for (int im = 0; im < 4; im++)
                ldsm_x4(af[im], a_base + im * (16 * SH * 2) + ks * 32);
            uint32_t bf[4][4];   // bf[p]: n-tiles 2p,2p+1 (k0-7 then k8-15)
#pragma unroll
            for (int p = 0; p < 4; p++)
                ldsm_x4(bf[p], b_base + p * (16 * SH * 2) + ks * 32);
#pragma unroll
            for (int im = 0; im < 4; im++)
#pragma unroll
                for (int in = 0; in < 8; in++)
                    mma_f16(acc[im][in], af[im],
                            bf[in >> 1][in & 1], bf[in >> 1][(in & 1) + 2]);
        }
    }
    cp_wait<0>();

    // ---- epilogue ----
#pragma unroll
    for (int im = 0; im < 4; im++) {
        const int row = m0 + wm0 + im * 16 + grp;
#pragma unroll
        for (int in = 0; in < 8; in++) {
            const int col = n0 + wn0 + in * 8 + tg * 2;
            const float sc = (!QKVF || col < DIM) ? alpha : 1.0f;
            float2 v01, v23;
            v01.x = acc[im][in][0];
            v01.y = acc[im][in][1];
            v23.x = acc[im][in][2];
            v23.y = acc[im][in][3];
            if (BIAS) {
                const float2 bv = *reinterpret_cast<const float2*>(bias + col);
                v01.x += bv.x; v01.y += bv.y;
                v23.x += bv.x; v23.y += bv.y;
            }
            v01.x *= sc; v01.y *= sc; v23.x *= sc; v23.y *= sc;
            if (sizeof(CT) == 2) {
                *reinterpret_cast<__half2*>((__half*)C + (size_t)row * ldc + col)
                    = __floats2half2_rn(v01.x, v01.y);
                *reinterpret_cast<__half2*>((__half*)C + (size_t)(row + 8) * ldc + col)
                    = __floats2half2_rn(v23.x, v23.y);
            } else {
                *reinterpret_cast<float2*>((float*)C + (size_t)row * ldc + col) = v01;
                *reinterpret_cast<float2*>((float*)C + (size_t)(row + 8) * ldc + col) = v23;
            }
        }
    }
}

// ----------------------------------------------------------------------------
// fp32 -> fp16 elementwise copy
// ----------------------------------------------------------------------------
__global__ __launch_bounds__(256)
void f32_to_f16(const float* __restrict__ src, __half* __restrict__ dst)
{
    const int i = blockIdx.x * blockDim.x + threadIdx.x;
    const float4 v = reinterpret_cast<const float4*>(src)[i];
    __half2* d = reinterpret_cast<__half2*>(dst) + i * 2;
    d[0] = __floats2half2_rn(v.x, v.y);
    d[1] = __floats2half2_rn(v.z, v.w);
}

// ----------------------------------------------------------------------------
// 32x32 tiled transpose, fp32 src -> fp16 dst (square DIM x DIM blocks)
// ----------------------------------------------------------------------------
__global__ __launch_bounds__(256)
void trans_f2h(const float* __restrict__ src, __half* __restrict__ dst,
               int R, int C)
{
    __shared__ float t[32][33];
    const int r0 = blockIdx.y * 32, c0 = blockIdx.x * 32;
    const int tx = threadIdx.x & 31, ty = threadIdx.x >> 5;
#pragma unroll
    for (int i = 0; i < 4; i++)
        t[ty + 8 * i][tx] = src[(size_t)(r0 + ty + 8 * i) * C + c0 + tx];
    __syncthreads();
#pragma unroll
    for (int i = 0; i < 4; i++)
        dst[(size_t)(c0 + ty + 8 * i) * R + r0 + tx] =
            __float2half_rn(t[tx][ty + 8 * i]);
}

// ----------------------------------------------------------------------------
// 32x32 tiled transpose fp16->fp16 with src leading dim (batched via z)
//   dst[c*Rd + r] = src[r*ldS + c]
// ----------------------------------------------------------------------------
__global__ __launch_bounds__(256)
void trans_h2h(const __half* __restrict__ src, __half* __restrict__ dst,
               int Rd, int ldS, size_t sS, size_t sD)
{
    __shared__ __half t[32][34];
    src += (size_t)blockIdx.z * sS;
    dst += (size_t)blockIdx.z * sD;
    const int r0 = blockIdx.y * 32, c0 = blockIdx.x * 32;
    const int tx = threadIdx.x & 31, ty = threadIdx.x >> 5;
#pragma unroll
    for (int i = 0; i < 4; i++)
        t[ty + 8 * i][tx] = src[(size_t)(r0 + ty + 8 * i) * ldS + c0 + tx];
    __syncthreads();
#pragma unroll
    for (int i = 0; i < 4; i++)
        dst[(size_t)(c0 + ty + 8 * i) * Rd + r0 + tx] = t[tx][ty + 8 * i];
}

// ----------------------------------------------------------------------------
// bias concat: bc[0:768)=bq, [768:1536)=bk, [1536:2304)=bv
// ----------------------------------------------------------------------------
__global__ void concat_bias(const float* __restrict__ bq,
                            const float* __restrict__ bk,
                            const float* __restrict__ bv,
                            float* __restrict__ bc)
{
    const int i = blockIdx.x * blockDim.x + threadIdx.x;
    if (i < DIM)            bc[i] = bq[i];
    else if (i < 2 * DIM)   bc[i] = bk[i - DIM];
    else if (i < 3 * DIM)   bc[i] = bv[i - 2 * DIM];
}

// ----------------------------------------------------------------------------
// Row softmax over SEQ=2048 fp32 scores -> fp16 probs.
// ----------------------------------------------------------------------------
__global__ __launch_bounds__(256)
void softmax2048(const float* __restrict__ S, __half* __restrict__ P)
{
    const float* p = S + (size_t)blockIdx.x * SEQ;
    __half2* po = reinterpret_cast<__half2*>(P + (size_t)blockIdx.x * SEQ);
    const int tid = threadIdx.x;
    __shared__ float red_max[8];
    __shared__ float red_sum[8];

    const float4* p4 = reinterpret_cast<const float4*>(p);
    float4 vals[2];

    float m = -1e30f;
#pragma unroll
    for (int r = 0; r < 2; r++) {
        const float4 v = p4[tid + r * 256];
        vals[r] = v;
        m = fmaxf(m, fmaxf(fmaxf(v.x, v.y), fmaxf(v.z, v.w)));
    }
#pragma unroll
    for (int o = 16; o > 0; o >>= 1)
        m = fmaxf(m, __shfl_xor_sync(0xffffffffu, m, o));
    if ((tid & 31) == 0) red_max[tid >> 5] = m;
    __syncthreads();
    float rm = red_max[0];
#pragma unroll
    for (int i = 1; i < 8; i++) rm = fmaxf(rm, red_max[i]);

    float s = 0.0f;
#pragma unroll
    for (int r = 0; r < 2; r++) {
        float4 v = vals[r];
        v.x = __expf(v.x - rm);
        v.y = __expf(v.y - rm);
        v.z = __expf(v.z - rm);
        v.w = __expf(v.w - rm);
        s += v.x + v.y + v.z + v.w;
        vals[r] = v;
    }
#pragma unroll
    for (int o = 16; o > 0; o >>= 1)
        s += __shfl_xor_sync(0xffffffffu, s, o);
    if ((tid & 31) == 0) red_sum[tid >> 5] = s;
    __syncthreads();
    float total = 0.0f;
#pragma unroll
    for (int i = 0; i < 8; i++) total += red_sum[i];
    const float inv = 1.0f / total;

#pragma unroll
    for (int r = 0; r < 2; r++) {
        const float4 v = vals[r];
        const int i = tid + r * 256;
        po[i * 2 + 0] = __floats2half2_rn(v.x * inv, v.y * inv);
        po[i * 2 + 1] = __floats2half2_rn(v.z * inv, v.w * inv);
    }
}

// ----------------------------------------------------------------------------
// kernel_launch
// Inputs: x[B,S,D], Wq[D,D], bq[D], Wk, bk, Wv, bv ; output [B,S,D] fp32
// ----------------------------------------------------------------------------
extern "C" void kernel_launch(void* const* d_in, const int* in_sizes, int n_in,
                              void* d_out, int out_size)
{
    const float* x  = (const float*)d_in[0];
    const float* Wq = (const float*)d_in[1];
    const float* bq = (const float*)d_in[2];
    const float* Wk = (const float*)d_in[3];
    const float* bk = (const float*)d_in[4];
    const float* Wv = (const float*)d_in[5];
    const float* bv = (const float*)d_in[6];
    float* out = (float*)d_out;

    __half *xh, *qkv, *vt, *p, *wt;
    float *s, *bc;
    cudaGetSymbolAddress((void**)&xh,  g_xh);
    cudaGetSymbolAddress((void**)&qkv, g_qkv);
    cudaGetSymbolAddress((void**)&vt,  g_vt);
    cudaGetSymbolAddress((void**)&s,   g_s);
    cudaGetSymbolAddress((void**)&p,   g_p);
    cudaGetSymbolAddress((void**)&wt,  g_wt);
    cudaGetSymbolAddress((void**)&bc,  g_bc);

    const int SMEM_DYN = NSTAGE * STAGE_H * (int)sizeof(__half);   // 110592 B
    cudaFuncSetAttribute((const void*)gemm_h<__half, true, true>,
                         cudaFuncAttributeMaxDynamicSharedMemorySize, SMEM_DYN);
    cudaFuncSetAttribute((const void*)gemm_h<float, false, false>,
                         cudaFuncAttributeMaxDynamicSharedMemorySize, SMEM_DYN);

    const size_t sQKV = (size_t)SEQ * NQKV;   // per-batch qkv stride
    const size_t sSD  = (size_t)SEQ * DIM;
    const size_t sSS  = (size_t)SEQ * SEQ;

    // 0) x -> fp16 ; W -> half(W^T) concatenated ; bias concat
    f32_to_f16<<<(BATCH * SEQ * DIM / 4 + 255) / 256, 256>>>(x, xh);
    {
        const dim3 g(DIM / 32, DIM / 32, 1);
        trans_f2h<<<g, 256>>>(Wq, wt,                         DIM, DIM);
        trans_f2h<<<g, 256>>>(Wk, wt + (size_t)DIM * DIM,     DIM, DIM);
        trans_f2h<<<g, 256>>>(Wv, wt + 2 * (size_t)DIM * DIM, DIM, DIM);
    }
    concat_bias<<<(NQKV + 255) / 256, 256>>>(bq, bk, bv, bc);

    // 1) fused QKV: [8192,2304] = x @ Wcat^T + bcat ; Q slice pre-scaled 1/sqrt(D)
    {
        const dim3 g(NQKV / 128, (BATCH * SEQ) / 128, 1);
        gemm_h<__half, true, true><<<g, 128, SMEM_DYN>>>(
            xh, wt, bc, qkv, DIM, DIM, DIM, NQKV,
            rsqrtf((float)DIM), 0, 0, 0);
    }

    // 2) transpose V slice: [S, D] (ld=NQKV) -> vt [D, S] per batch
    {
        const dim3 g(DIM / 32, SEQ / 32, BATCH);
        trans_h2h<<<g, 256>>>(qkv + 2 * DIM, vt, SEQ, NQKV, sQKV, sSD);
    }

    // 3) scores = Qs @ K^T  (Q already scaled; NT, fp32 out)
    {
        const dim3 g(SEQ / 128, SEQ / 128, BATCH);
        gemm_h<float, false, false><<<g, 128, SMEM_DYN>>>(
            qkv, qkv + DIM, nullptr, s, DIM, NQKV, NQKV, SEQ,
            1.0f, sQKV, sQKV, sSS);
    }

    // 4) softmax rows: fp32 scores -> fp16 probs
    softmax2048<<<BATCH * SEQ, 256>>>(s, p);

    // 5) out = P @ V == p[S,S] @ (vt[D,S])^T  (NT, fp32 out)
    {
        const dim3 g(DIM / 128, SEQ / 128, BATCH);
        gemm_h<float, false, false><<<g, 128, SMEM_DYN>>>(
            p, vt, nullptr, out, SEQ, SEQ, SEQ, DIM,
            1.0f, sSS, sSD, sSD);
    }
}

// round 9
// speedup vs baseline: 1.8292x; 1.0043x over previous
#include <cuda_runtime.h>
#include <cuda_fp16.h>
#include <math.h>
#include <stdint.h>

// Problem constants
#define BATCH 4
#define SEQ   2048
#define DIM   768
#define NQKV  (3 * DIM)        // 2304

// Scratch (allocation-free: __device__ globals)
__device__ __half g_xh  [(size_t)BATCH * SEQ * DIM];
__device__ __half g_qkv [(size_t)BATCH * SEQ * NQKV];
__device__ __half g_vt  [(size_t)BATCH * SEQ * DIM];
__device__ float  g_s   [(size_t)BATCH * SEQ * SEQ];
__device__ __half g_p   [(size_t)BATCH * SEQ * SEQ];
__device__ __half g_wt  [(size_t)NQKV * DIM];
__device__ float  g_bc  [NQKV];

// ----------------------------------------------------------------------------
// helpers
// ----------------------------------------------------------------------------
__device__ __forceinline__ uint32_t smem_u32(const void* p) {
    uint32_t a;
    asm("{ .reg .u64 t; cvta.to.shared.u64 t, %1; cvt.u32.u64 %0, t; }"
        : "=r"(a) : "l"(p));
    return a;
}
__device__ __forceinline__ void cp_async16(uint32_t dst, const void* src) {
    asm volatile("cp.async.cg.shared.global [%0], [%1], 16;"
                 :: "r"(dst), "l"(src));
}
__device__ __forceinline__ void cp_commit() {
    asm volatile("cp.async.commit_group;" ::: "memory");
}
template <int N>
__device__ __forceinline__ void cp_wait() {
    asm volatile("cp.async.wait_group %0;" :: "n"(N) : "memory");
}
__device__ __forceinline__ void ldsm_x4(uint32_t* r, uint32_t addr) {
    asm volatile("ldmatrix.sync.aligned.m8n8.x4.shared.b16 {%0,%1,%2,%3}, [%4];"
                 : "=r"(r[0]), "=r"(r[1]), "=r"(r[2]), "=r"(r[3])
                 : "r"(addr));
}
__device__ __forceinline__ void mma_f16(float* c, const uint32_t* a,
                                        uint32_t b0, uint32_t b1) {
    asm volatile(
        "mma.sync.aligned.m16n8k16.row.col.f32.f16.f16.f32 "
        "{%0,%1,%2,%3}, {%4,%5,%6,%7}, {%8,%9}, {%0,%1,%2,%3};"
        : "+f"(c[0]), "+f"(c[1]), "+f"(c[2]), "+f"(c[3])
        : "r"(a[0]), "r"(a[1]), "r"(a[2]), "r"(a[3]),
          "r"(b0), "r"(b1));
}

// ----------------------------------------------------------------------------
// fp16 tensor-core GEMM (NT): C = scale * (A @ B^T + bias)
//   A: [M,K] half row-major (lda), B: [N,K] half row-major (ldb)
//   C: [M,N] float or half (ldc). fp32 accumulate.
//   CTA tile 128x128, 4 warps, warp tile 64x64 (4x8 m16n8k16 atoms).
//   BK=64, 3-stage cp.async pipeline. SMEM row stride 72 halfs (144B).
//   QKVF: per-column scale — cols < DIM get alpha (Q pre-scale), else 1.
// ----------------------------------------------------------------------------
#define SH        72
#define MAT_H     (128 * SH)
#define STAGE_H   (2 * MAT_H)            // A tile + B tile (halfs)
#define NSTAGE    3

template <typename CT, bool BIAS, bool QKVF>
__global__ __launch_bounds__(128)
void gemm_h(const __half* __restrict__ A, const __half* __restrict__ B,
            const float* __restrict__ bias, CT* __restrict__ C,
            int K, int lda, int ldb, int ldc, float alpha,
            size_t sA, size_t sB, size_t sC)
{
    extern __shared__ __half smh[];

    const int tid  = threadIdx.x;
    const int wid  = tid >> 5;
    const int lane = tid & 31;
    const int grp  = lane >> 2;
    const int tg   = lane & 3;
    const int wm0  = (wid & 1) * 64;
    const int wn0  = (wid >> 1) * 64;
    const int lg   = lane >> 3;
    const int lrow = lane & 7;

    A += (size_t)blockIdx.z * sA;
    B += (size_t)blockIdx.z * sB;
    C += (size_t)blockIdx.z * sC;
    const int m0 = blockIdx.y * 128;
    const int n0 = blockIdx.x * 128;

    // gmem->smem: 16B granules; 8 segs per 64-half row; 128 threads
    const int ld_row = tid >> 3;        // 0..15 (+16 per pass, 8 passes)
    const int ld_seg = tid & 7;

    float acc[4][8][4];
#pragma unroll
    for (int im = 0; im < 4; im++)
#pragma unroll
        for (int in = 0; in < 8; in++)
#pragma unroll
            for (int r = 0; r < 4; r++) acc[im][in][r] = 0.0f;

    const int nch = K >> 6;

    auto load_tile = [&](int c) {
        const int kt = c << 6;
        __half* as = smh + (c % NSTAGE) * STAGE_H;
        __half* bs = as + MAT_H;
        const uint32_t as_u = smem_u32(as);
        const uint32_t bs_u = smem_u32(bs);
#pragma unroll
        for (int r = 0; r < 8; r++) {
            const int row = ld_row + r * 16;
            cp_async16(as_u + (uint32_t)(row * SH + ld_seg * 8) * 2,
                       A + (size_t)(m0 + row) * lda + kt + ld_seg * 8);
        }
#pragma unroll
        for (int r = 0; r < 8; r++) {
            const int row = ld_row + r * 16;
            cp_async16(bs_u + (uint32_t)(row * SH + ld_seg * 8) * 2,
                       B + (size_t)(n0 + row) * ldb + kt + ld_seg * 8);
        }
    };

    load_tile(0);
    cp_commit();
    load_tile(1);
    cp_commit();

    for (int c = 0; c < nch; c++) {
        cp_wait<1>();          // stage c resident (c+1 may be in flight)
        __syncthreads();       // visibility + all warps done with stage c-1

        if (c + 2 < nch) {     // prefetch into buffer (c+2)%3 == (c-1)%3 (free)
            load_tile(c + 2);
            cp_commit();
        }

        const __half* as = smh + (c % NSTAGE) * STAGE_H;
        const __half* bs = as + MAT_H;

        const uint32_t a_base = smem_u32(as) +
            (uint32_t)(((wm0 + (lg & 1) * 8 + lrow) * SH + (lg >> 1) * 8) * 2);
        const uint32_t b_base = smem_u32(bs) +
            (uint32_t)(((wn0 + (lg & 1) * 8 + lrow) * SH + (lg >> 1) * 8) * 2);

#pragma unroll
        for (int ks = 0; ks < 4; ks++) {
            uint32_t af[4][4];
#pragma unroll
            for (int im = 0; im < 4; im++)
                ldsm_x4(af[im], a_base + im * (16 * SH * 2) + ks * 32);
            uint32_t bf[4][4];   // bf[p]: n-tiles 2p,2p+1 (k0-7 then k8-15)
#pragma unroll
            for (int p = 0; p < 4; p++)
                ldsm_x4(bf[p], b_base + p * (16 * SH * 2) + ks * 32);
#pragma unroll
            for (int im = 0; im < 4; im++)
#pragma unroll
                for (int in = 0; in < 8; in++)
                    mma_f16(acc[im][in], af[im],
                            bf[in >> 1][in & 1], bf[in >> 1][(in & 1) + 2]);
        }
    }
    cp_wait<0>();

    // ---- epilogue ----
#pragma unroll
    for (int im = 0; im < 4; im++) {
        const int row = m0 + wm0 + im * 16 + grp;
#pragma unroll
        for (int in = 0; in < 8; in++) {
            const int col = n0 + wn0 + in * 8 + tg * 2;
            const float sc = (!QKVF || col < DIM) ? alpha : 1.0f;
            float2 v01, v23;
            v01.x = acc[im][in][0];
            v01.y = acc[im][in][1];
            v23.x = acc[im][in][2];
            v23.y = acc[im][in][3];
            if (BIAS) {
                const float2 bv = *reinterpret_cast<const float2*>(bias + col);
                v01.x += bv.x; v01.y += bv.y;
                v23.x += bv.x; v23.y += bv.y;
            }
            v01.x *= sc; v01.y *= sc; v23.x *= sc; v23.y *= sc;
            if (sizeof(CT) == 2) {
                *reinterpret_cast<__half2*>((__half*)C + (size_t)row * ldc + col)
                    = __floats2half2_rn(v01.x, v01.y);
                *reinterpret_cast<__half2*>((__half*)C + (size_t)(row + 8) * ldc + col)
                    = __floats2half2_rn(v23.x, v23.y);
            } else {
                *reinterpret_cast<float2*>((float*)C + (size_t)row * ldc + col) = v01;
                *reinterpret_cast<float2*>((float*)C + (size_t)(row + 8) * ldc + col) = v23;
            }
        }
    }
}

// ----------------------------------------------------------------------------
// fp32 -> fp16 elementwise copy
// ----------------------------------------------------------------------------
__global__ __launch_bounds__(256)
void f32_to_f16(const float* __restrict__ src, __half* __restrict__ dst)
{
    const int i = blockIdx.x * blockDim.x + threadIdx.x;
    const float4 v = reinterpret_cast<const float4*>(src)[i];
    __half2* d = reinterpret_cast<__half2*>(dst) + i * 2;
    d[0] = __floats2half2_rn(v.x, v.y);
    d[1] = __floats2half2_rn(v.z, v.w);
}

// ----------------------------------------------------------------------------
// 32x32 tiled transpose, fp32 src -> fp16 dst (square DIM x DIM blocks)
// ----------------------------------------------------------------------------
__global__ __launch_bounds__(256)
void trans_f2h(const float* __restrict__ src, __half* __restrict__ dst,
               int R, int C)
{
    __shared__ float t[32][33];
    const int r0 = blockIdx.y * 32, c0 = blockIdx.x * 32;
    const int tx = threadIdx.x & 31, ty = threadIdx.x >> 5;
#pragma unroll
    for (int i = 0; i < 4; i++)
        t[ty + 8 * i][tx] = src[(size_t)(r0 + ty + 8 * i) * C + c0 + tx];
    __syncthreads();
#pragma unroll
    for (int i = 0; i < 4; i++)
        dst[(size_t)(c0 + ty + 8 * i) * R + r0 + tx] =
            __float2half_rn(t[tx][ty + 8 * i]);
}

// ----------------------------------------------------------------------------
// 32x32 tiled transpose fp16->fp16 with src leading dim (batched via z)
//   dst[c*Rd + r] = src[r*ldS + c]
// ----------------------------------------------------------------------------
__global__ __launch_bounds__(256)
void trans_h2h(const __half* __restrict__ src, __half* __restrict__ dst,
               int Rd, int ldS, size_t sS, size_t sD)
{
    __shared__ __half t[32][34];
    src += (size_t)blockIdx.z * sS;
    dst += (size_t)blockIdx.z * sD;
    const int r0 = blockIdx.y * 32, c0 = blockIdx.x * 32;
    const int tx = threadIdx.x & 31, ty = threadIdx.x >> 5;
#pragma unroll
    for (int i = 0; i < 4; i++)
        t[ty + 8 * i][tx] = src[(size_t)(r0 + ty + 8 * i) * ldS + c0 + tx];
    __syncthreads();
#pragma unroll
    for (int i = 0; i < 4; i++)
        dst[(size_t)(c0 + ty + 8 * i) * Rd + r0 + tx] = t[tx][ty + 8 * i];
}

// ----------------------------------------------------------------------------
// bias concat: bc[0:768)=bq, [768:1536)=bk, [1536:2304)=bv
// ----------------------------------------------------------------------------
__global__ void concat_bias(const float* __restrict__ bq,
                            const float* __restrict__ bk,
                            const float* __restrict__ bv,
                            float* __restrict__ bc)
{
    const int i = blockIdx.x * blockDim.x + threadIdx.x;
    if (i < DIM)            bc[i] = bq[i];
    else if (i < 2 * DIM)   bc[i] = bk[i - DIM];
    else if (i < 3 * DIM)   bc[i] = bv[i - 2 * DIM];
}

// ----------------------------------------------------------------------------
// Row softmax over SEQ=2048 fp32 scores -> fp16 probs.
// ----------------------------------------------------------------------------
__global__ __launch_bounds__(256)
void softmax2048(const float* __restrict__ S, __half* __restrict__ P)
{
    const float* p = S + (size_t)blockIdx.x * SEQ;
    __half2* po = reinterpret_cast<__half2*>(P + (size_t)blockIdx.x * SEQ);
    const int tid = threadIdx.x;
    __shared__ float red_max[8];
    __shared__ float red_sum[8];

    const float4* p4 = reinterpret_cast<const float4*>(p);
    float4 vals[2];

    float m = -1e30f;
#pragma unroll
    for (int r = 0; r < 2; r++) {
        const float4 v = p4[tid + r * 256];
        vals[r] = v;
        m = fmaxf(m, fmaxf(fmaxf(v.x, v.y), fmaxf(v.z, v.w)));
    }
#pragma unroll
    for (int o = 16; o > 0; o >>= 1)
        m = fmaxf(m, __shfl_xor_sync(0xffffffffu, m, o));
    if ((tid & 31) == 0) red_max[tid >> 5] = m;
    __syncthreads();
    float rm = red_max[0];
#pragma unroll
    for (int i = 1; i < 8; i++) rm = fmaxf(rm, red_max[i]);

    float s = 0.0f;
#pragma unroll
    for (int r = 0; r < 2; r++) {
        float4 v = vals[r];
        v.x = __expf(v.x - rm);
        v.y = __expf(v.y - rm);
        v.z = __expf(v.z - rm);
        v.w = __expf(v.w - rm);
        s += v.x + v.y + v.z + v.w;
        vals[r] = v;
    }
#pragma unroll
    for (int o = 16; o > 0; o >>= 1)
        s += __shfl_xor_sync(0xffffffffu, s, o);
    if ((tid & 31) == 0) red_sum[tid >> 5] = s;
    __syncthreads();
    float total = 0.0f;
#pragma unroll
    for (int i = 0; i < 8; i++) total += red_sum[i];
    const float inv = 1.0f / total;

#pragma unroll
    for (int r = 0; r < 2; r++) {
        const float4 v = vals[r];
        const int i = tid + r * 256;
        po[i * 2 + 0] = __floats2half2_rn(v.x * inv, v.y * inv);
        po[i * 2 + 1] = __floats2half2_rn(v.z * inv, v.w * inv);
    }
}

// ----------------------------------------------------------------------------
// kernel_launch
// Inputs: x[B,S,D], Wq[D,D], bq[D], Wk, bk, Wv, bv ; output [B,S,D] fp32
// ----------------------------------------------------------------------------
extern "C" void kernel_launch(void* const* d_in, const int* in_sizes, int n_in,
                              void* d_out, int out_size)
{
    const float* x  = (const float*)d_in[0];
    const float* Wq = (const float*)d_in[1];
    const float* bq = (const float*)d_in[2];
    const float* Wk = (const float*)d_in[3];
    const float* bk = (const float*)d_in[4];
    const float* Wv = (const float*)d_in[5];
    const float* bv = (const float*)d_in[6];
    float* out = (float*)d_out;

    __half *xh, *qkv, *vt, *p, *wt;
    float *s, *bc;
    cudaGetSymbolAddress((void**)&xh,  g_xh);
    cudaGetSymbolAddress((void**)&qkv, g_qkv);
    cudaGetSymbolAddress((void**)&vt,  g_vt);
    cudaGetSymbolAddress((void**)&s,   g_s);
    cudaGetSymbolAddress((void**)&p,   g_p);
    cudaGetSymbolAddress((void**)&wt,  g_wt);
    cudaGetSymbolAddress((void**)&bc,  g_bc);

    const int SMEM_DYN = NSTAGE * STAGE_H * (int)sizeof(__half);   // 110592 B
    cudaFuncSetAttribute((const void*)gemm_h<__half, true, true>,
                         cudaFuncAttributeMaxDynamicSharedMemorySize, SMEM_DYN);
    cudaFuncSetAttribute((const void*)gemm_h<float, false, false>,
                         cudaFuncAttributeMaxDynamicSharedMemorySize, SMEM_DYN);

    const size_t sQKV = (size_t)SEQ * NQKV;   // per-batch qkv stride
    const size_t sSD  = (size_t)SEQ * DIM;
    const size_t sSS  = (size_t)SEQ * SEQ;

    // 0) x -> fp16 ; W -> half(W^T) concatenated ; bias concat
    f32_to_f16<<<(BATCH * SEQ * DIM / 4 + 255) / 256, 256>>>(x, xh);
    {
        const dim3 g(DIM / 32, DIM / 32, 1);
        trans_f2h<<<g, 256>>>(Wq, wt,                         DIM, DIM);
        trans_f2h<<<g, 256>>>(Wk, wt + (size_t)DIM * DIM,     DIM, DIM);
        trans_f2h<<<g, 256>>>(Wv, wt + 2 * (size_t)DIM * DIM, DIM, DIM);
    }
    concat_bias<<<(NQKV + 255) / 256, 256>>>(bq, bk, bv, bc);

    // 1) fused QKV: [8192,2304] = x @ Wcat^T + bcat ; Q slice pre-scaled 1/sqrt(D)
    {
        const dim3 g(NQKV / 128, (BATCH * SEQ) / 128, 1);
        gemm_h<__half, true, true><<<g, 128, SMEM_DYN>>>(
            xh, wt, bc, qkv, DIM, DIM, DIM, NQKV,
            rsqrtf((float)DIM), 0, 0, 0);
    }

    // 2) transpose V slice: [S, D] (ld=NQKV) -> vt [D, S] per batch
    {
        const dim3 g(DIM / 32, SEQ / 32, BATCH);
        trans_h2h<<<g, 256>>>(qkv + 2 * DIM, vt, SEQ, NQKV, sQKV, sSD);
    }

    // 3) scores = Qs @ K^T  (Q already scaled; NT, fp32 out)
    {
        const dim3 g(SEQ / 128, SEQ / 128, BATCH);
        gemm_h<float, false, false><<<g, 128, SMEM_DYN>>>(
            qkv, qkv + DIM, nullptr, s, DIM, NQKV, NQKV, SEQ,
            1.0f, sQKV, sQKV, sSS);
    }

    // 4) softmax rows: fp32 scores -> fp16 probs
    softmax2048<<<BATCH * SEQ, 256>>>(s, p);

    // 5) out = P @ V == p[S,S] @ (vt[D,S])^T  (NT, fp32 out)
    {
        const dim3 g(DIM / 128, SEQ / 128, BATCH);
        gemm_h<float, false, false><<<g, 128, SMEM_DYN>>>(
            p, vt, nullptr, out, SEQ, SEQ, SEQ, DIM,
            1.0f, sSS, sSD, sSD);
    }
}